// round 14
// baseline (speedup 1.0000x reference)
#include <cuda_runtime.h>
#include <math.h>

#define NN 5000
#define NL 20000
#define NP 50000

typedef unsigned long long ull;

// ------------------------- device-global scratch -------------------------
__device__ __align__(16) float g_link[2][NL * 32];
__device__ __align__(16) float g_node[2][NN * 32];
__device__ __align__(16) float g_path[NP * 64];
__device__ __align__(16) float g_m[NL * 64];
__device__ __align__(16) float g_Lx[NL * 192];
__device__ __align__(16) float g_Nx[NN * 192];
__device__ __align__(16) float g_z[(size_t)NN * 1056];
__device__ __align__(16) float g_W2[32768];
__device__ __align__(16) float g_wpack[12288];
__device__ __align__(16) float g_b1pack[192];
__device__ __align__(16) float g_We[4096];
__device__ __align__(16) float g_be[32];

// ------------------------------ helpers ----------------------------------
__device__ __forceinline__ float sigm(float x) {
    return __fdividef(1.0f, 1.0f + __expf(-x));
}
__device__ __forceinline__ float tanh_fast(float x) {
    float ax = fabsf(x);
    float e  = __expf(-2.0f * ax);
    float t  = __fdividef(1.0f - e, 1.0f + e);
    return copysignf(t, x);
}
__device__ __forceinline__ float selu_f(float x) {
    return x > 0.0f ? 1.0507009873554805f * x
                    : 1.7580993408473766f * (__expf(x) - 1.0f);
}
__device__ __forceinline__ void red4(float* a, float x, float y, float z, float w) {
    asm volatile("red.global.add.v4.f32 [%0], {%1,%2,%3,%4};"
                 :: "l"(a), "f"(x), "f"(y), "f"(z), "f"(w) : "memory");
}
__device__ __forceinline__ ull pack2(float a, float b) {
    ull r; asm("mov.b64 %0, {%1,%2};" : "=l"(r) : "f"(a), "f"(b)); return r;
}
__device__ __forceinline__ void ffma2(ull& acc, ull a, ull b) {
    asm("fma.rn.f32x2 %0, %1, %2, %0;" : "+l"(acc) : "l"(a), "l"(b));
}
__device__ __forceinline__ void unpack2(ull v, float& lo, float& hi) {
    asm("mov.b64 {%0,%1}, %2;" : "=f"(lo), "=f"(hi) : "l"(v));
}

// ------------- merged prep: gru pack | fused edge MLP | W2 permute --------
__global__ void prep_all_k(const float* __restrict__ wh, const float* __restrict__ b,
                           const float* __restrict__ w1, const float* __restrict__ b1,
                           const float* __restrict__ w2, const float* __restrict__ b2,
                           const float* __restrict__ wk) {
    int idx = blockIdx.x * 256 + threadIdx.x;
    if (idx < 12288) {
        int k = idx & 3;
        int q = idx >> 2;           // quad index = (i*3 + g)*16 + jg
        int jg = q & 15;
        int g  = (q >> 4) % 3;
        int i  = (q >> 4) / 3;
        g_wpack[idx] = wh[i * 192 + g * 64 + jg * 4 + k];
    } else if (idx < 12480) {
        int r = idx - 12288;
        int k = r & 3;
        int g = (r >> 2) % 3;
        int jg = (r >> 2) / 3;
        g_b1pack[r] = b[192 + g * 64 + jg * 4 + k];
    } else if (idx < 12480 + 4096) {
        int r = idx - 12480;
        int c = r >> 5, j = r & 31;
        float acc = 0.0f;
        #pragma unroll
        for (int k = 0; k < 32; k++) acc += w1[c * 32 + k] * w2[k * 32 + j];
        g_We[r] = acc;
    } else if (idx < 12480 + 4128) {
        int j = idx - 12480 - 4096;
        float acc = b2[j];
        #pragma unroll
        for (int k = 0; k < 32; k++) acc += b1[k] * w2[k * 32 + j];
        g_be[j] = acc;
    } else if (idx < 12480 + 4128 + 32768) {
        int r = idx - 16608;
        int o = r & 31;
        int i = (r >> 5) & 31;
        int c = r >> 10;
        g_W2[i * 1024 + c * 32 + o] = wk[r];
    }
}

// -------------- merged init: link | node | path | zero m ------------------
__global__ void init_all_k(const float* __restrict__ li,
                           const float* __restrict__ ni,
                           const float* __restrict__ pi) {
    int idx = blockIdx.x * 256 + threadIdx.x;   // 5,280,000 total
    if (idx < NL * 32) {
        int l = idx >> 5, c = idx & 31;
        g_link[0][idx] = (c == 0) ? li[l] : 0.0f;
    } else if (idx < NL * 32 + NN * 32) {
        int r = idx - NL * 32;
        int n = r >> 5, c = r & 31;
        g_node[0][r] = (c == 0) ? ni[n] : 0.0f;
    } else if (idx < NL * 32 + NN * 32 + NP * 64) {
        int r = idx - NL * 32 - NN * 32;
        int p = r >> 6, c = r & 63;
        float v = 0.0f;
        if (c == 0) v = pi[p];
        else if (c == 1) v = pi[NP + p];
        g_path[r] = v;
    } else {
        g_m[idx - 4000000] = 0.0f;
    }
}

// ------ iter-1 Lx/Nx fast path (states are rank-1: only col 0 nonzero) ----
__global__ void __launch_bounds__(192) lxnx1_kernel(const float* __restrict__ wx,
                                                    const float* __restrict__ b,
                                                    const float* __restrict__ li,
                                                    const float* __restrict__ ni) {
    int tid = threadIdx.x;
    bool is_link = (blockIdx.x < 2500);
    int base = is_link ? blockIdx.x * 8 : (blockIdx.x - 2500) * 8;
    float wj = is_link ? wx[tid] : wx[6144 + tid];
    float bj = is_link ? b[tid] : 0.0f;
    const float* init = is_link ? li : ni;
    float* dst = is_link ? g_Lx : g_Nx;
    #pragma unroll
    for (int e = 0; e < 8; e++) {
        float v = init[base + e];
        dst[(size_t)(base + e) * 192 + tid] = v * wj + bj;
    }
}

// ---------- iter-2 node Nx (post-ECC): 625 blocks ------------------------
__global__ void __launch_bounds__(192) nx2_kernel(const float* __restrict__ wx, int cur) {
    __shared__ float swx[6144];
    __shared__ float sst[8][33];
    int tid = threadIdx.x;
    for (int r = tid; r < 6144; r += 192) swx[r] = wx[6144 + r];
    const float* st = g_node[cur];
    int base = blockIdx.x * 8;
    for (int r = tid; r < 256; r += 192) {
        int e = r >> 5, c = r & 31;
        sst[e][c] = st[(size_t)(base + e) * 32 + c];
    }
    __syncthreads();
    int j = tid;
    for (int e = 0; e < 8; e++) {
        float acc = 0.0f;
        #pragma unroll
        for (int i = 0; i < 32; i++) acc += sst[e][i] * swx[i * 192 + j];
        g_Nx[(size_t)(base + e) * 192 + j] = acc;
    }
}

// --------------------------- fused GRU scan ------------------------------
// h stored TRANSPOSED: shh[buf][p*68 + j]
#define GRU_SMEM_BYTES 84736

#define GRU_SUB(i, v0, v1, v2, v3)                                           \
    {                                                                        \
        ulonglong2 wz = w2m[((i) * 3 + 0) * 16 + jg];                        \
        ulonglong2 wr = w2m[((i) * 3 + 1) * 16 + jg];                        \
        ulonglong2 wh = w2m[((i) * 3 + 2) * 16 + jg];                        \
        ull hp0 = pack2(v0, v0);                                             \
        ull hp1 = pack2(v1, v1);                                             \
        ull hp2 = pack2(v2, v2);                                             \
        ull hp3 = pack2(v3, v3);                                             \
        ffma2(a2[0][0], hp0, wz.x); ffma2(a2[0][1], hp0, wz.y);              \
        ffma2(a2[0][2], hp0, wr.x); ffma2(a2[0][3], hp0, wr.y);              \
        ffma2(a2[0][4], hp0, wh.x); ffma2(a2[0][5], hp0, wh.y);              \
        ffma2(a2[1][0], hp1, wz.x); ffma2(a2[1][1], hp1, wz.y);              \
        ffma2(a2[1][2], hp1, wr.x); ffma2(a2[1][3], hp1, wr.y);              \
        ffma2(a2[1][4], hp1, wh.x); ffma2(a2[1][5], hp1, wh.y);              \
        ffma2(a2[2][0], hp2, wz.x); ffma2(a2[2][1], hp2, wz.y);              \
        ffma2(a2[2][2], hp2, wr.x); ffma2(a2[2][3], hp2, wr.y);              \
        ffma2(a2[2][4], hp2, wh.x); ffma2(a2[2][5], hp2, wh.y);              \
        ffma2(a2[3][0], hp3, wz.x); ffma2(a2[3][1], hp3, wz.y);              \
        ffma2(a2[3][2], hp3, wr.x); ffma2(a2[3][3], hp3, wr.y);              \
        ffma2(a2[3][4], hp3, wh.x); ffma2(a2[3][5], hp3, wh.y);              \
    }

template <int SCATTER, int FIRST, int FINAL>
__global__ void __launch_bounds__(256, 2) gru_kernel(
    const int* __restrict__ l2p, const int* __restrict__ n2p,
    const float* __restrict__ rw1, const float* __restrict__ rb1,
    const float* __restrict__ rw2, const float* __restrict__ rb2,
    const float* __restrict__ fw,  const float* __restrict__ fb,
    float* __restrict__ out) {
    extern __shared__ float sm[];
    float4* wsm = (float4*)sm;               // 3072 quads
    float*  sb1 = sm + 12288;                // 192
    float*  shh = sm + 12480;                // 2 * 4352  ([p][68] layout)

    int tid = threadIdx.x;
    int pg = tid >> 4, jg = tid & 15;
    int pbase = blockIdx.x * 64;

    const float4* wgl = (const float4*)g_wpack;
    #pragma unroll
    for (int r = 0; r < 12; r++) wsm[r * 256 + tid] = wgl[r * 256 + tid];
    if (tid < 192) sb1[tid] = g_b1pack[tid];

    // stage h transposed: shh[p*68 + j]
    const float4* gp4 = (const float4*)g_path;
    #pragma unroll
    for (int r = 0; r < 4; r++) {
        int idx = r * 256 + tid;
        int p = idx >> 4, iq = idx & 15;
        int pglob = pbase + p; if (pglob >= NP) pglob = NP - 1;
        float4 v = gp4[(size_t)pglob * 16 + iq];
        *(float4*)(shh + p * 68 + iq * 4) = v;
    }
    __syncthreads();

    const ulonglong2* sb2 = (const ulonglong2*)sb1;
    ulonglong2 bA = sb2[jg * 3 + 0];
    ulonglong2 bB = sb2[jg * 3 + 1];
    ulonglong2 bC = sb2[jg * 3 + 2];

    int pid[4]; bool pv[4];
    #pragma unroll
    for (int pp = 0; pp < 4; pp++) {
        int pglob = pbase + pg * 4 + pp;
        pv[pp] = (pglob < NP);
        pid[pp] = pv[pp] ? pglob : NP - 1;
    }
    const int hb0 = (pg * 4 + 0) * 68;
    const int hb1 = (pg * 4 + 1) * 68;
    const int hb2 = (pg * 4 + 2) * 68;
    const int hb3 = (pg * 4 + 3) * 68;

    const float4* Lx4 = (const float4*)g_Lx;
    const float4* Nx4 = (const float4*)g_Nx;
    const ulonglong2* w2m = (const ulonglong2*)wsm;

    int hbuf = 0;
    for (int t = 0; t < 8; t++) {
        float4 gz[4], gr[4], gc[4];
        int liA[4];
        #pragma unroll
        for (int pp = 0; pp < 4; pp++) {
            int e = pid[pp] * 8 + t;
            int li = l2p[e], ni = n2p[e];
            liA[pp] = li;
            const float4* lq = Lx4 + (size_t)li * 48 + jg;
            const float4* nq = Nx4 + (size_t)ni * 48 + jg;
            float4 a0 = lq[0],  b0 = nq[0];
            float4 a1 = lq[16], b1 = nq[16];
            float4 a2q = lq[32], b2q = nq[32];
            gz[pp] = make_float4(a0.x + b0.x, a0.y + b0.y, a0.z + b0.z, a0.w + b0.w);
            gr[pp] = make_float4(a1.x + b1.x, a1.y + b1.y, a1.z + b1.z, a1.w + b1.w);
            gc[pp] = make_float4(a2q.x + b2q.x, a2q.y + b2q.y, a2q.z + b2q.z, a2q.w + b2q.w);
        }

        float* shH  = shh + hbuf * 4352;
        float* shHn = shh + (hbuf ^ 1) * 4352;

        ull a2[4][6];
        #pragma unroll
        for (int pp = 0; pp < 4; pp++) {
            a2[pp][0] = bA.x; a2[pp][1] = bA.y;
            a2[pp][2] = bB.x; a2[pp][3] = bB.y;
            a2[pp][4] = bC.x; a2[pp][5] = bC.y;
        }

        if (FIRST && t == 0) {
            float2 h20 = *(const float2*)(shH + hb0);
            float2 h21 = *(const float2*)(shH + hb1);
            float2 h22 = *(const float2*)(shH + hb2);
            float2 h23 = *(const float2*)(shH + hb3);
            GRU_SUB(0, h20.x, h21.x, h22.x, h23.x);
            GRU_SUB(1, h20.y, h21.y, h22.y, h23.y);
        } else {
            #pragma unroll 2
            for (int i4 = 0; i4 < 64; i4 += 4) {
                float4 h40 = *(const float4*)(shH + hb0 + i4);
                float4 h41 = *(const float4*)(shH + hb1 + i4);
                float4 h42 = *(const float4*)(shH + hb2 + i4);
                float4 h43 = *(const float4*)(shH + hb3 + i4);
                GRU_SUB(i4 + 0, h40.x, h41.x, h42.x, h43.x);
                GRU_SUB(i4 + 1, h40.y, h41.y, h42.y, h43.y);
                GRU_SUB(i4 + 2, h40.z, h41.z, h42.z, h43.z);
                GRU_SUB(i4 + 3, h40.w, h41.w, h42.w, h43.w);
            }
        }

        int j0 = jg * 4;
        #pragma unroll
        for (int pp = 0; pp < 4; pp++) {
            int p = pg * 4 + pp;
            float az0, az1, az2, az3, ar0, ar1, ar2, ar3, ah0, ah1, ah2, ah3;
            unpack2(a2[pp][0], az0, az1); unpack2(a2[pp][1], az2, az3);
            unpack2(a2[pp][2], ar0, ar1); unpack2(a2[pp][3], ar2, ar3);
            unpack2(a2[pp][4], ah0, ah1); unpack2(a2[pp][5], ah2, ah3);
            float z0 = sigm(gz[pp].x + az0);
            float z1 = sigm(gz[pp].y + az1);
            float z2 = sigm(gz[pp].z + az2);
            float z3 = sigm(gz[pp].w + az3);
            float r0 = sigm(gr[pp].x + ar0);
            float r1 = sigm(gr[pp].y + ar1);
            float r2 = sigm(gr[pp].z + ar2);
            float r3 = sigm(gr[pp].w + ar3);
            float c0 = tanh_fast(gc[pp].x + r0 * ah0);
            float c1 = tanh_fast(gc[pp].y + r1 * ah1);
            float c2 = tanh_fast(gc[pp].z + r2 * ah2);
            float c3 = tanh_fast(gc[pp].w + r3 * ah3);
            float4 hold = *(const float4*)(shH + p * 68 + j0);
            float n0 = z0 * hold.x + (1.0f - z0) * c0;
            float n1 = z1 * hold.y + (1.0f - z1) * c1;
            float n2 = z2 * hold.z + (1.0f - z2) * c2;
            float n3 = z3 * hold.w + (1.0f - z3) * c3;
            *(float4*)(shHn + p * 68 + j0) = make_float4(n0, n1, n2, n3);
            if (SCATTER && pv[pp]) {
                red4(g_m + (size_t)liA[pp] * 64 + j0, n0, n1, n2, n3);
            }
        }
        hbuf ^= 1;
        __syncthreads();
    }

    float* shF = shh + hbuf * 4352;

    if (!FINAL) {
        // write path_state back (consumed by iter-2 gru)
        #pragma unroll
        for (int r = 0; r < 4; r++) {
            int idx = r * 256 + tid;
            int p = idx >> 4, iq = idx & 15;
            int pglob = pbase + p;
            if (pglob < NP) {
                float4 v = *(const float4*)(shF + p * 68 + iq * 4);
                ((float4*)g_path)[(size_t)pglob * 16 + iq] = v;
            }
        }
    } else {
        // ---- inline readout (overwrite weight smem; h already in shF) ----
        float* sw1  = sm;            // 2048
        float* sw2  = sm + 2048;     // 1024
        float* sfw  = sm + 3072;     // 96
        float* srb1 = sm + 3200;     // 32
        float* srb2 = sm + 3232;     // 32
        float* sr1a = sm + 3264;     // 8 * 33
        for (int r = tid; r < 2048; r += 256) sw1[r] = rw1[r];
        for (int r = tid; r < 1024; r += 256) sw2[r] = rw2[r];
        if (tid < 96) sfw[tid] = fw[tid];
        if (tid < 32) srb1[tid] = rb1[tid];
        else if (tid < 64) srb2[tid - 32] = rb2[tid - 32];
        __syncthreads();
        int w = tid >> 5, lane = tid & 31;
        float rb1l = srb1[lane], rb2l = srb2[lane], fb0 = fb[0];
        #pragma unroll
        for (int it = 0; it < 8; it++) {
            int pl = w * 8 + it;
            int pglob = pbase + pl;
            const float* hrow = shF + pl * 68;
            float acc = rb1l;
            #pragma unroll
            for (int i = 0; i < 64; i++) acc += hrow[i] * sw1[i * 32 + lane];
            float r1v = selu_f(acc);
            sr1a[w * 33 + lane] = r1v;
            __syncwarp();
            float acc2 = rb2l;
            #pragma unroll
            for (int i = 0; i < 32; i++) acc2 += sr1a[w * 33 + i] * sw2[i * 32 + lane];
            float r2v = selu_f(acc2);
            float part = r2v * sfw[lane] + hrow[lane] * sfw[32 + lane]
                       + hrow[32 + lane] * sfw[64 + lane];
            #pragma unroll
            for (int o = 16; o; o >>= 1) part += __shfl_down_sync(0xffffffffu, part, o);
            if (lane == 0 && pglob < NP) out[pglob] = part + fb0;
            __syncwarp();
        }
    }
}

// ------- z[s][c*32+o] = sum_i node[s][i] * W2[i][c*32+o];  + beta cols ----
__global__ void __launch_bounds__(256) z_kernel(const float* __restrict__ bk, int cur) {
    __shared__ __align__(16) float Ns[512];
    int tid = threadIdx.x;
    int n0 = blockIdx.x * 16;
    const float* nst = g_node[cur];
    for (int r = tid; r < 512; r += 256) {
        int i = r >> 4, nl = r & 15;
        int nn = n0 + nl; if (nn >= NN) nn = NN - 1;
        Ns[r] = nst[(size_t)nn * 32 + i];
    }
    __syncthreads();
    int o = blockIdx.y * 512 + tid;
    ull acc0[8], acc1[8];
    #pragma unroll
    for (int q = 0; q < 8; q++) { acc0[q] = 0ull; acc1[q] = 0ull; }
    for (int i = 0; i < 32; i++) {
        float w0 = g_W2[i * 1024 + o];
        float w1 = g_W2[i * 1024 + o + 256];
        ull w0p = pack2(w0, w0);
        ull w1p = pack2(w1, w1);
        const ulonglong2* np = (const ulonglong2*)(Ns + i * 16);
        #pragma unroll
        for (int q2 = 0; q2 < 4; q2++) {
            ulonglong2 nv = np[q2];
            ffma2(acc0[q2 * 2 + 0], nv.x, w0p);
            ffma2(acc0[q2 * 2 + 1], nv.y, w0p);
            ffma2(acc1[q2 * 2 + 0], nv.x, w1p);
            ffma2(acc1[q2 * 2 + 1], nv.y, w1p);
        }
    }
    #pragma unroll
    for (int q = 0; q < 8; q++) {
        float v0, v1, u0, u1;
        unpack2(acc0[q], v0, v1);
        unpack2(acc1[q], u0, u1);
        int na = n0 + 2 * q, nb = n0 + 2 * q + 1;
        if (na < NN) { g_z[(size_t)na * 1056 + o] = v0; g_z[(size_t)na * 1056 + o + 256] = u0; }
        if (nb < NN) { g_z[(size_t)nb * 1056 + o] = v1; g_z[(size_t)nb * 1056 + o + 256] = u1; }
    }
    if (blockIdx.y == 0) {
        int nl = tid >> 5;
        int oo = tid & 31;
        float b0 = 0.0f, b1 = 0.0f;
        #pragma unroll
        for (int i = 0; i < 32; i++) {
            float bkv = bk[i * 32 + oo];
            b0 += Ns[i * 16 + nl] * bkv;
            b1 += Ns[i * 16 + nl + 8] * bkv;
        }
        if (n0 + nl < NN)     g_z[(size_t)(n0 + nl) * 1056 + 1024 + oo] = b0;
        if (n0 + nl + 8 < NN) g_z[(size_t)(n0 + nl + 8) * 1056 + 1024 + oo] = b1;
    }
}

// --------- root (stores): node1 = broot + node0@wroot ---------------------
__global__ void __launch_bounds__(256) root_kernel(const float* __restrict__ wroot,
                                                   const float* __restrict__ broot,
                                                   int cur, int nxt) {
    __shared__ float sw[1024];
    int tid = threadIdx.x;
    for (int i = tid; i < 1024; i += 256) sw[i] = wroot[i];
    __syncthreads();
    int w = tid >> 5, lane = tid & 31;
    int n = blockIdx.x * 8 + w;
    const float* nr = g_node[cur] + (size_t)n * 32;
    float acc = broot[lane];
    #pragma unroll
    for (int i = 0; i < 32; i++) acc += nr[i] * sw[i * 32 + lane];
    g_node[nxt][(size_t)n * 32 + lane] = acc;
}

// ----- fused edge MLP + ECC message + iter-2 link Lx ----------------------
__global__ void __launch_bounds__(256) edge_msg_lx_kernel(
    const int* __restrict__ l2n, const int* __restrict__ senders,
    const int* __restrict__ recv, const float* __restrict__ wx,
    const float* __restrict__ gb, int cur, int nxt) {
    __shared__ float sWe[4096];
    __shared__ float swxL[6144];
    __shared__ float sbx[192];
    __shared__ float sbe[32];
    __shared__ float con[8][128];
    __shared__ float sL[8][32];
    int tid = threadIdx.x;
    for (int i = tid; i < 4096; i += 256) sWe[i] = g_We[i];
    for (int i = tid; i < 6144; i += 256) swxL[i] = wx[i];
    if (tid < 192) sbx[tid] = gb[tid] + (tid < 128 ? gb[192 + tid] : 0.0f);
    if (tid < 32) sbe[tid] = g_be[tid];
    int w = tid >> 5, lane = tid & 31;
    int l = blockIdx.x * 8 + w;
    int nn = l2n[l];
    con[w][lane]      = g_node[cur][(size_t)nn * 32 + lane];
    con[w][32 + lane] = g_link[cur][(size_t)l * 32 + lane];
    con[w][64 + lane] = g_m[(size_t)l * 64 + lane];
    con[w][96 + lane] = g_m[(size_t)l * 64 + 32 + lane];
    __syncthreads();
    float acc = sbe[lane];
    #pragma unroll
    for (int c = 0; c < 128; c++) acc += con[w][c] * sWe[c * 32 + lane];
    sL[w][lane] = acc;
    __syncwarp();
    // ECC message via z
    int s = senders[l];
    const float* zr = g_z + (size_t)s * 1056;
    float macc = zr[1024 + lane];
    #pragma unroll
    for (int c = 0; c < 32; c++) macc += sL[w][c] * zr[c * 32 + lane];
    atomicAdd(&g_node[nxt][(size_t)recv[l] * 32 + lane], macc);
    // iter-2 Lx from link' (same op order as old lxnx link branch)
    #pragma unroll
    for (int k = 0; k < 6; k++) {
        int jj = k * 32 + lane;
        float a = sbx[jj];
        #pragma unroll
        for (int c = 0; c < 32; c++) a += sL[w][c] * swxL[c * 192 + jj];
        g_Lx[(size_t)l * 192 + jj] = a;
    }
}

// ---------------------------- launcher ------------------------------------
extern "C" void kernel_launch(void* const* d_in, const int* in_sizes, int n_in,
                              void* d_out, int out_size) {
    const float* link_init = (const float*)d_in[0];
    const float* node_init = (const float*)d_in[1];
    const float* path_init = (const float*)d_in[2];
    const float* gru_wx    = (const float*)d_in[3];
    const float* gru_wh    = (const float*)d_in[4];
    const float* gru_b     = (const float*)d_in[5];
    const float* e_w1      = (const float*)d_in[6];
    const float* e_b1      = (const float*)d_in[7];
    const float* e_w2      = (const float*)d_in[8];
    const float* e_b2      = (const float*)d_in[9];
    const float* ecc_wk    = (const float*)d_in[10];
    const float* ecc_bk    = (const float*)d_in[11];
    const float* ecc_wroot = (const float*)d_in[12];
    const float* ecc_broot = (const float*)d_in[13];
    const float* r_w1      = (const float*)d_in[14];
    const float* r_b1      = (const float*)d_in[15];
    const float* r_w2      = (const float*)d_in[16];
    const float* r_b2      = (const float*)d_in[17];
    const float* f_w       = (const float*)d_in[18];
    const float* f_b       = (const float*)d_in[19];
    const int* l2p   = (const int*)d_in[22];
    const int* n2p   = (const int*)d_in[23];
    const int* l2n   = (const int*)d_in[24];
    const int* senders   = (const int*)d_in[25];
    const int* receivers = (const int*)d_in[26];
    float* out = (float*)d_out;

    cudaFuncSetAttribute((const void*)gru_kernel<1, 1, 0>,
                         cudaFuncAttributeMaxDynamicSharedMemorySize, GRU_SMEM_BYTES);
    cudaFuncSetAttribute((const void*)gru_kernel<0, 0, 1>,
                         cudaFuncAttributeMaxDynamicSharedMemorySize, GRU_SMEM_BYTES);

    prep_all_k<<<193, 256>>>(gru_wh, gru_b, e_w1, e_b1, e_w2, e_b2, ecc_wk);   // 0
    init_all_k<<<20625, 256>>>(link_init, node_init, path_init);               // 1
    lxnx1_kernel<<<3125, 192>>>(gru_wx, gru_b, link_init, node_init);          // 2
    gru_kernel<1, 1, 0><<<782, 256, GRU_SMEM_BYTES>>>(
        l2p, n2p, r_w1, r_b1, r_w2, r_b2, f_w, f_b, out);                      // 3
    z_kernel<<<dim3(313, 2), 256>>>(ecc_bk, 0);                                // 4
    root_kernel<<<625, 256>>>(ecc_wroot, ecc_broot, 0, 1);                     // 5
    edge_msg_lx_kernel<<<2500, 256>>>(l2n, senders, receivers,
                                      gru_wx, gru_b, 0, 1);                    // 6
    nx2_kernel<<<625, 192>>>(gru_wx, 1);                                       // 7
    gru_kernel<0, 0, 1><<<782, 256, GRU_SMEM_BYTES>>>(
        l2p, n2p, r_w1, r_b1, r_w2, r_b2, f_w, f_b, out);                      // 8
}

// round 15
// speedup vs baseline: 1.0583x; 1.0583x over previous
#include <cuda_runtime.h>
#include <math.h>

#define NN 5000
#define NL 20000
#define NP 50000

typedef unsigned long long ull;

// ------------------------- device-global scratch -------------------------
__device__ __align__(16) float g_node1[NN * 32];      // node state after ECC
__device__ __align__(16) float g_path[NP * 64];
__device__ __align__(16) float g_m[NL * 64];
__device__ __align__(16) float g_Lx[NL * 192];
__device__ __align__(16) float g_Nx[NN * 192];
__device__ __align__(16) float g_wpack[12288];
__device__ __align__(16) float g_b1pack[192];
__device__ __align__(16) float g_We[4096];
__device__ __align__(16) float g_be[32];

// ------------------------------ helpers ----------------------------------
__device__ __forceinline__ float sigm(float x) {
    return __fdividef(1.0f, 1.0f + __expf(-x));
}
__device__ __forceinline__ float tanh_fast(float x) {
    float ax = fabsf(x);
    float e  = __expf(-2.0f * ax);
    float t  = __fdividef(1.0f - e, 1.0f + e);
    return copysignf(t, x);
}
__device__ __forceinline__ float selu_f(float x) {
    return x > 0.0f ? 1.0507009873554805f * x
                    : 1.7580993408473766f * (__expf(x) - 1.0f);
}
__device__ __forceinline__ void red4(float* a, float x, float y, float z, float w) {
    asm volatile("red.global.add.v4.f32 [%0], {%1,%2,%3,%4};"
                 :: "l"(a), "f"(x), "f"(y), "f"(z), "f"(w) : "memory");
}
__device__ __forceinline__ ull pack2(float a, float b) {
    ull r; asm("mov.b64 %0, {%1,%2};" : "=l"(r) : "f"(a), "f"(b)); return r;
}
__device__ __forceinline__ void ffma2(ull& acc, ull a, ull b) {
    asm("fma.rn.f32x2 %0, %1, %2, %0;" : "+l"(acc) : "l"(a), "l"(b));
}
__device__ __forceinline__ void unpack2(ull v, float& lo, float& hi) {
    asm("mov.b64 {%0,%1}, %2;" : "=f"(lo), "=f"(hi) : "l"(v));
}

// ------------- merged prep: gru pack | fused edge MLP ---------------------
__global__ void prep_all_k(const float* __restrict__ wh, const float* __restrict__ b,
                           const float* __restrict__ w1, const float* __restrict__ b1,
                           const float* __restrict__ w2, const float* __restrict__ b2) {
    int idx = blockIdx.x * 256 + threadIdx.x;
    if (idx < 12288) {
        int k = idx & 3;
        int q = idx >> 2;           // quad index = (i*3 + g)*16 + jg
        int jg = q & 15;
        int g  = (q >> 4) % 3;
        int i  = (q >> 4) / 3;
        g_wpack[idx] = wh[i * 192 + g * 64 + jg * 4 + k];
    } else if (idx < 12480) {
        int r = idx - 12288;
        int k = r & 3;
        int g = (r >> 2) % 3;
        int jg = (r >> 2) / 3;
        g_b1pack[r] = b[192 + g * 64 + jg * 4 + k];
    } else if (idx < 12480 + 4096) {
        int r = idx - 12480;
        int c = r >> 5, j = r & 31;
        float acc = 0.0f;
        #pragma unroll
        for (int k = 0; k < 32; k++) acc += w1[c * 32 + k] * w2[k * 32 + j];
        g_We[r] = acc;
    } else if (idx < 12480 + 4128) {
        int j = idx - 12480 - 4096;
        float acc = b2[j];
        #pragma unroll
        for (int k = 0; k < 32; k++) acc += b1[k] * w2[k * 32 + j];
        g_be[j] = acc;
    }
}

// -------------- init: path state + zero m (float4) ------------------------
__global__ void init4_k(const float* __restrict__ pi) {
    int idx = blockIdx.x * 256 + threadIdx.x;   // 1,120,000 quads
    if (idx < 800000) {
        int p = idx >> 4, q = idx & 15;
        float4 v = make_float4(0.f, 0.f, 0.f, 0.f);
        if (q == 0) { v.x = pi[p]; v.y = pi[NP + p]; }
        ((float4*)g_path)[idx] = v;
    } else {
        ((float4*)g_m)[idx - 800000] = make_float4(0.f, 0.f, 0.f, 0.f);
    }
}

// ------ iter-1 Lx/Nx fast path (states rank-1: only col 0 nonzero) --------
__global__ void __launch_bounds__(192) lxnx1_kernel(const float* __restrict__ wx,
                                                    const float* __restrict__ b,
                                                    const float* __restrict__ li,
                                                    const float* __restrict__ ni) {
    int tid = threadIdx.x;
    bool is_link = (blockIdx.x < 2500);
    int base = is_link ? blockIdx.x * 8 : (blockIdx.x - 2500) * 8;
    float wj = is_link ? wx[tid] : wx[6144 + tid];
    float bj = is_link ? b[tid] : 0.0f;
    const float* init = is_link ? li : ni;
    float* dst = is_link ? g_Lx : g_Nx;
    #pragma unroll
    for (int e = 0; e < 8; e++) {
        float v = init[base + e];
        dst[(size_t)(base + e) * 192 + tid] = v * wj + bj;
    }
}

// ---------- iter-2 node Nx (post-ECC): 625 blocks ------------------------
__global__ void __launch_bounds__(192) nx2_kernel(const float* __restrict__ wx) {
    __shared__ float swx[6144];
    __shared__ float sst[8][33];
    int tid = threadIdx.x;
    for (int r = tid; r < 6144; r += 192) swx[r] = wx[6144 + r];
    int base = blockIdx.x * 8;
    for (int r = tid; r < 256; r += 192) {
        int e = r >> 5, c = r & 31;
        sst[e][c] = g_node1[(size_t)(base + e) * 32 + c];
    }
    __syncthreads();
    int j = tid;
    for (int e = 0; e < 8; e++) {
        float acc = 0.0f;
        #pragma unroll
        for (int i = 0; i < 32; i++) acc += sst[e][i] * swx[i * 192 + j];
        g_Nx[(size_t)(base + e) * 192 + j] = acc;
    }
}

// --------------------------- fused GRU scan ------------------------------
#define GRU_SMEM_BYTES 84736

#define GRU_SUB(i, v0, v1, v2, v3)                                           \
    {                                                                        \
        ulonglong2 wz = w2m[((i) * 3 + 0) * 16 + jg];                        \
        ulonglong2 wr = w2m[((i) * 3 + 1) * 16 + jg];                        \
        ulonglong2 wh = w2m[((i) * 3 + 2) * 16 + jg];                        \
        ull hp0 = pack2(v0, v0);                                             \
        ull hp1 = pack2(v1, v1);                                             \
        ull hp2 = pack2(v2, v2);                                             \
        ull hp3 = pack2(v3, v3);                                             \
        ffma2(a2[0][0], hp0, wz.x); ffma2(a2[0][1], hp0, wz.y);              \
        ffma2(a2[0][2], hp0, wr.x); ffma2(a2[0][3], hp0, wr.y);              \
        ffma2(a2[0][4], hp0, wh.x); ffma2(a2[0][5], hp0, wh.y);              \
        ffma2(a2[1][0], hp1, wz.x); ffma2(a2[1][1], hp1, wz.y);              \
        ffma2(a2[1][2], hp1, wr.x); ffma2(a2[1][3], hp1, wr.y);              \
        ffma2(a2[1][4], hp1, wh.x); ffma2(a2[1][5], hp1, wh.y);              \
        ffma2(a2[2][0], hp2, wz.x); ffma2(a2[2][1], hp2, wz.y);              \
        ffma2(a2[2][2], hp2, wr.x); ffma2(a2[2][3], hp2, wr.y);              \
        ffma2(a2[2][4], hp2, wh.x); ffma2(a2[2][5], hp2, wh.y);              \
        ffma2(a2[3][0], hp3, wz.x); ffma2(a2[3][1], hp3, wz.y);              \
        ffma2(a2[3][2], hp3, wr.x); ffma2(a2[3][3], hp3, wr.y);              \
        ffma2(a2[3][4], hp3, wh.x); ffma2(a2[3][5], hp3, wh.y);              \
    }

template <int SCATTER, int FIRST, int FINAL>
__global__ void __launch_bounds__(256, 2) gru_kernel(
    const int* __restrict__ l2p, const int* __restrict__ n2p,
    const float* __restrict__ rw1, const float* __restrict__ rb1,
    const float* __restrict__ rw2, const float* __restrict__ rb2,
    const float* __restrict__ fw,  const float* __restrict__ fb,
    float* __restrict__ out) {
    extern __shared__ float sm[];
    float4* wsm = (float4*)sm;               // 3072 quads
    float*  sb1 = sm + 12288;                // 192
    float*  shh = sm + 12480;                // 2 * 4352  ([p][68] layout)

    int tid = threadIdx.x;
    int pg = tid >> 4, jg = tid & 15;
    int pbase = blockIdx.x * 64;

    const float4* wgl = (const float4*)g_wpack;
    #pragma unroll
    for (int r = 0; r < 12; r++) wsm[r * 256 + tid] = wgl[r * 256 + tid];
    if (tid < 192) sb1[tid] = g_b1pack[tid];

    const float4* gp4 = (const float4*)g_path;
    #pragma unroll
    for (int r = 0; r < 4; r++) {
        int idx = r * 256 + tid;
        int p = idx >> 4, iq = idx & 15;
        int pglob = pbase + p; if (pglob >= NP) pglob = NP - 1;
        float4 v = gp4[(size_t)pglob * 16 + iq];
        *(float4*)(shh + p * 68 + iq * 4) = v;
    }
    __syncthreads();

    const ulonglong2* sb2 = (const ulonglong2*)sb1;
    ulonglong2 bA = sb2[jg * 3 + 0];
    ulonglong2 bB = sb2[jg * 3 + 1];
    ulonglong2 bC = sb2[jg * 3 + 2];

    int pid[4]; bool pv[4];
    #pragma unroll
    for (int pp = 0; pp < 4; pp++) {
        int pglob = pbase + pg * 4 + pp;
        pv[pp] = (pglob < NP);
        pid[pp] = pv[pp] ? pglob : NP - 1;
    }
    const int hb0 = (pg * 4 + 0) * 68;
    const int hb1 = (pg * 4 + 1) * 68;
    const int hb2 = (pg * 4 + 2) * 68;
    const int hb3 = (pg * 4 + 3) * 68;

    const float4* Lx4 = (const float4*)g_Lx;
    const float4* Nx4 = (const float4*)g_Nx;
    const ulonglong2* w2m = (const ulonglong2*)wsm;

    int hbuf = 0;
    for (int t = 0; t < 8; t++) {
        float4 gz[4], gr[4], gc[4];
        int liA[4];
        #pragma unroll
        for (int pp = 0; pp < 4; pp++) {
            int e = pid[pp] * 8 + t;
            int li = l2p[e], ni = n2p[e];
            liA[pp] = li;
            const float4* lq = Lx4 + (size_t)li * 48 + jg;
            const float4* nq = Nx4 + (size_t)ni * 48 + jg;
            float4 a0 = lq[0],  b0 = nq[0];
            float4 a1 = lq[16], b1 = nq[16];
            float4 a2q = lq[32], b2q = nq[32];
            gz[pp] = make_float4(a0.x + b0.x, a0.y + b0.y, a0.z + b0.z, a0.w + b0.w);
            gr[pp] = make_float4(a1.x + b1.x, a1.y + b1.y, a1.z + b1.z, a1.w + b1.w);
            gc[pp] = make_float4(a2q.x + b2q.x, a2q.y + b2q.y, a2q.z + b2q.z, a2q.w + b2q.w);
        }

        float* shH  = shh + hbuf * 4352;
        float* shHn = shh + (hbuf ^ 1) * 4352;

        ull a2[4][6];
        #pragma unroll
        for (int pp = 0; pp < 4; pp++) {
            a2[pp][0] = bA.x; a2[pp][1] = bA.y;
            a2[pp][2] = bB.x; a2[pp][3] = bB.y;
            a2[pp][4] = bC.x; a2[pp][5] = bC.y;
        }

        if (FIRST && t == 0) {
            float2 h20 = *(const float2*)(shH + hb0);
            float2 h21 = *(const float2*)(shH + hb1);
            float2 h22 = *(const float2*)(shH + hb2);
            float2 h23 = *(const float2*)(shH + hb3);
            GRU_SUB(0, h20.x, h21.x, h22.x, h23.x);
            GRU_SUB(1, h20.y, h21.y, h22.y, h23.y);
        } else {
            #pragma unroll 2
            for (int i4 = 0; i4 < 64; i4 += 4) {
                float4 h40 = *(const float4*)(shH + hb0 + i4);
                float4 h41 = *(const float4*)(shH + hb1 + i4);
                float4 h42 = *(const float4*)(shH + hb2 + i4);
                float4 h43 = *(const float4*)(shH + hb3 + i4);
                GRU_SUB(i4 + 0, h40.x, h41.x, h42.x, h43.x);
                GRU_SUB(i4 + 1, h40.y, h41.y, h42.y, h43.y);
                GRU_SUB(i4 + 2, h40.z, h41.z, h42.z, h43.z);
                GRU_SUB(i4 + 3, h40.w, h41.w, h42.w, h43.w);
            }
        }

        int j0 = jg * 4;
        #pragma unroll
        for (int pp = 0; pp < 4; pp++) {
            int p = pg * 4 + pp;
            float az0, az1, az2, az3, ar0, ar1, ar2, ar3, ah0, ah1, ah2, ah3;
            unpack2(a2[pp][0], az0, az1); unpack2(a2[pp][1], az2, az3);
            unpack2(a2[pp][2], ar0, ar1); unpack2(a2[pp][3], ar2, ar3);
            unpack2(a2[pp][4], ah0, ah1); unpack2(a2[pp][5], ah2, ah3);
            float z0 = sigm(gz[pp].x + az0);
            float z1 = sigm(gz[pp].y + az1);
            float z2 = sigm(gz[pp].z + az2);
            float z3 = sigm(gz[pp].w + az3);
            float r0 = sigm(gr[pp].x + ar0);
            float r1 = sigm(gr[pp].y + ar1);
            float r2 = sigm(gr[pp].z + ar2);
            float r3 = sigm(gr[pp].w + ar3);
            float c0 = tanh_fast(gc[pp].x + r0 * ah0);
            float c1 = tanh_fast(gc[pp].y + r1 * ah1);
            float c2 = tanh_fast(gc[pp].z + r2 * ah2);
            float c3 = tanh_fast(gc[pp].w + r3 * ah3);
            float4 hold = *(const float4*)(shH + p * 68 + j0);
            float n0 = z0 * hold.x + (1.0f - z0) * c0;
            float n1 = z1 * hold.y + (1.0f - z1) * c1;
            float n2 = z2 * hold.z + (1.0f - z2) * c2;
            float n3 = z3 * hold.w + (1.0f - z3) * c3;
            *(float4*)(shHn + p * 68 + j0) = make_float4(n0, n1, n2, n3);
            if (SCATTER && pv[pp]) {
                red4(g_m + (size_t)liA[pp] * 64 + j0, n0, n1, n2, n3);
            }
        }
        hbuf ^= 1;
        __syncthreads();
    }

    float* shF = shh + hbuf * 4352;

    if (!FINAL) {
        #pragma unroll
        for (int r = 0; r < 4; r++) {
            int idx = r * 256 + tid;
            int p = idx >> 4, iq = idx & 15;
            int pglob = pbase + p;
            if (pglob < NP) {
                float4 v = *(const float4*)(shF + p * 68 + iq * 4);
                ((float4*)g_path)[(size_t)pglob * 16 + iq] = v;
            }
        }
    } else {
        // ---- inline readout (overwrite weight smem; h already in shF) ----
        float* sw1  = sm;            // 2048
        float* sw2  = sm + 2048;     // 1024
        float* sfw  = sm + 3072;     // 96
        float* srb1 = sm + 3200;     // 32
        float* srb2 = sm + 3232;     // 32
        float* sr1a = sm + 3264;     // 8 * 33
        for (int r = tid; r < 2048; r += 256) sw1[r] = rw1[r];
        for (int r = tid; r < 1024; r += 256) sw2[r] = rw2[r];
        if (tid < 96) sfw[tid] = fw[tid];
        if (tid < 32) srb1[tid] = rb1[tid];
        else if (tid < 64) srb2[tid - 32] = rb2[tid - 32];
        __syncthreads();
        int w = tid >> 5, lane = tid & 31;
        float rb1l = srb1[lane], rb2l = srb2[lane], fb0 = fb[0];
        #pragma unroll
        for (int it = 0; it < 8; it++) {
            int pl = w * 8 + it;
            int pglob = pbase + pl;
            const float* hrow = shF + pl * 68;
            float acc = rb1l;
            #pragma unroll
            for (int i = 0; i < 64; i++) acc += hrow[i] * sw1[i * 32 + lane];
            float r1v = selu_f(acc);
            sr1a[w * 33 + lane] = r1v;
            __syncwarp();
            float acc2 = rb2l;
            #pragma unroll
            for (int i = 0; i < 32; i++) acc2 += sr1a[w * 33 + i] * sw2[i * 32 + lane];
            float r2v = selu_f(acc2);
            float part = r2v * sfw[lane] + hrow[lane] * sfw[32 + lane]
                       + hrow[32 + lane] * sfw[64 + lane];
            #pragma unroll
            for (int o = 16; o; o >>= 1) part += __shfl_down_sync(0xffffffffu, part, o);
            if (lane == 0 && pglob < NP) out[pglob] = part + fb0;
            __syncwarp();
        }
    }
}

// --------- root (rank-1): node1 = broot + ni * wroot_row0 -----------------
__global__ void __launch_bounds__(256) root2_kernel(const float* __restrict__ wroot,
                                                    const float* __restrict__ broot,
                                                    const float* __restrict__ ni_in) {
    int tid = threadIdx.x;
    int w = tid >> 5, lane = tid & 31;
    int n = blockIdx.x * 8 + w;
    g_node1[(size_t)n * 32 + lane] = broot[lane] + ni_in[n] * wroot[lane];
}

// ----- fused edge MLP (rank-1 con) + ECC message (rank-1) + iter-2 Lx -----
#define EDGE_SMEM_BYTES 49152
__global__ void __launch_bounds__(256) edge_msg_lx_kernel(
    const int* __restrict__ l2n, const int* __restrict__ senders,
    const int* __restrict__ recv, const float* __restrict__ wx,
    const float* __restrict__ gb, const float* __restrict__ wk,
    const float* __restrict__ bk, const float* __restrict__ li_in,
    const float* __restrict__ ni_in) {
    extern __shared__ float es[];
    float* sWe  = es;            // 4096
    float* swxL = es + 4096;     // 6144
    float* sbx  = es + 10240;    // 192
    float* sbe  = es + 10432;    // 32
    float* swk  = es + 10464;    // 1024  (wk row block: swk[c*32+o] = wk[c*1024+o])
    float* sbk  = es + 11488;    // 32
    float* con  = es + 11520;    // 8*64 (m columns)
    float* sL   = es + 12032;    // 8*32
    int tid = threadIdx.x;
    for (int i = tid; i < 4096; i += 256) sWe[i] = g_We[i];
    for (int i = tid; i < 6144; i += 256) swxL[i] = wx[i];
    for (int i = tid; i < 1024; i += 256) {
        int c = i >> 5, o = i & 31;
        swk[i] = wk[c * 1024 + o];
    }
    if (tid < 192) sbx[tid] = gb[tid];
    if (tid < 32) sbe[tid] = g_be[tid];
    else if (tid < 64) sbk[tid - 32] = bk[tid - 32];
    int w = tid >> 5, lane = tid & 31;
    int l = blockIdx.x * 8 + w;
    con[w * 64 + lane]      = g_m[(size_t)l * 64 + lane];
    con[w * 64 + 32 + lane] = g_m[(size_t)l * 64 + 32 + lane];
    __syncthreads();
    int nn = l2n[l];
    float n0 = ni_in[nn];
    float lv = li_in[l];
    // edge MLP: exact-zero columns of con skipped (bit-exact)
    float acc = sbe[lane] + n0 * sWe[lane];
    acc += lv * sWe[1024 + lane];
    #pragma unroll
    for (int k = 0; k < 64; k++) acc += con[w * 64 + k] * sWe[(64 + k) * 32 + lane];
    sL[w * 32 + lane] = acc;
    __syncwarp();
    // ECC message (rank-1 sender): msg = ns * (bk_row0 + sum_c L'_c wk[c,0,o])
    float ns = ni_in[senders[l]];
    float q = sbk[lane];
    #pragma unroll
    for (int c = 0; c < 32; c++) q += sL[w * 32 + c] * swk[c * 32 + lane];
    atomicAdd(&g_node1[(size_t)recv[l] * 32 + lane], ns * q);
    // iter-2 link Lx from link' (b0 bias only; b1 handled in GRU b1pack)
    #pragma unroll
    for (int k = 0; k < 6; k++) {
        int jj = k * 32 + lane;
        float a = sbx[jj];
        #pragma unroll
        for (int c = 0; c < 32; c++) a += sL[w * 32 + c] * swxL[c * 192 + jj];
        g_Lx[(size_t)l * 192 + jj] = a;
    }
}

// ---------------------------- launcher ------------------------------------
extern "C" void kernel_launch(void* const* d_in, const int* in_sizes, int n_in,
                              void* d_out, int out_size) {
    const float* link_init = (const float*)d_in[0];
    const float* node_init = (const float*)d_in[1];
    const float* path_init = (const float*)d_in[2];
    const float* gru_wx    = (const float*)d_in[3];
    const float* gru_wh    = (const float*)d_in[4];
    const float* gru_b     = (const float*)d_in[5];
    const float* e_w1      = (const float*)d_in[6];
    const float* e_b1      = (const float*)d_in[7];
    const float* e_w2      = (const float*)d_in[8];
    const float* e_b2      = (const float*)d_in[9];
    const float* ecc_wk    = (const float*)d_in[10];
    const float* ecc_bk    = (const float*)d_in[11];
    const float* ecc_wroot = (const float*)d_in[12];
    const float* ecc_broot = (const float*)d_in[13];
    const float* r_w1      = (const float*)d_in[14];
    const float* r_b1      = (const float*)d_in[15];
    const float* r_w2      = (const float*)d_in[16];
    const float* r_b2      = (const float*)d_in[17];
    const float* f_w       = (const float*)d_in[18];
    const float* f_b       = (const float*)d_in[19];
    const int* l2p   = (const int*)d_in[22];
    const int* n2p   = (const int*)d_in[23];
    const int* l2n   = (const int*)d_in[24];
    const int* senders   = (const int*)d_in[25];
    const int* receivers = (const int*)d_in[26];
    float* out = (float*)d_out;

    cudaFuncSetAttribute((const void*)gru_kernel<1, 1, 0>,
                         cudaFuncAttributeMaxDynamicSharedMemorySize, GRU_SMEM_BYTES);
    cudaFuncSetAttribute((const void*)gru_kernel<0, 0, 1>,
                         cudaFuncAttributeMaxDynamicSharedMemorySize, GRU_SMEM_BYTES);
    cudaFuncSetAttribute((const void*)edge_msg_lx_kernel,
                         cudaFuncAttributeMaxDynamicSharedMemorySize, EDGE_SMEM_BYTES);

    prep_all_k<<<65, 256>>>(gru_wh, gru_b, e_w1, e_b1, e_w2, e_b2);            // 0
    init4_k<<<4375, 256>>>(path_init);                                         // 1
    lxnx1_kernel<<<3125, 192>>>(gru_wx, gru_b, link_init, node_init);          // 2
    gru_kernel<1, 1, 0><<<782, 256, GRU_SMEM_BYTES>>>(
        l2p, n2p, r_w1, r_b1, r_w2, r_b2, f_w, f_b, out);                      // 3
    root2_kernel<<<625, 256>>>(ecc_wroot, ecc_broot, node_init);               // 4
    edge_msg_lx_kernel<<<2500, 256, EDGE_SMEM_BYTES>>>(
        l2n, senders, receivers, gru_wx, gru_b, ecc_wk, ecc_bk,
        link_init, node_init);                                                 // 5
    nx2_kernel<<<625, 192>>>(gru_wx);                                          // 6
    gru_kernel<0, 0, 1><<<782, 256, GRU_SMEM_BYTES>>>(
        l2p, n2p, r_w1, r_b1, r_w2, r_b2, f_w, f_b, out);                      // 7
}

// round 16
// speedup vs baseline: 1.0824x; 1.0227x over previous
#include <cuda_runtime.h>
#include <math.h>

#define NN 5000
#define NL 20000
#define NP 50000

typedef unsigned long long ull;

// ------------------------- device-global scratch -------------------------
__device__ __align__(16) float g_node1[NN * 32];      // node state after ECC
__device__ __align__(16) float g_path[NP * 64];
__device__ __align__(16) float g_m[NL * 64];
__device__ __align__(16) float g_Lx[NL * 192];
__device__ __align__(16) float g_Nx[NN * 192];
__device__ __align__(16) float g_wpack[12288];
__device__ __align__(16) float g_b1pack[192];
__device__ __align__(16) float g_We[4096];
__device__ __align__(16) float g_be[32];

// ------------------------------ helpers ----------------------------------
__device__ __forceinline__ float sigm(float x) {
    return __fdividef(1.0f, 1.0f + __expf(-x));
}
__device__ __forceinline__ float tanh_fast(float x) {
    float ax = fabsf(x);
    float e  = __expf(-2.0f * ax);
    float t  = __fdividef(1.0f - e, 1.0f + e);
    return copysignf(t, x);
}
__device__ __forceinline__ float selu_f(float x) {
    return x > 0.0f ? 1.0507009873554805f * x
                    : 1.7580993408473766f * (__expf(x) - 1.0f);
}
__device__ __forceinline__ void red4(float* a, float x, float y, float z, float w) {
    asm volatile("red.global.add.v4.f32 [%0], {%1,%2,%3,%4};"
                 :: "l"(a), "f"(x), "f"(y), "f"(z), "f"(w) : "memory");
}
__device__ __forceinline__ ull pack2(float a, float b) {
    ull r; asm("mov.b64 %0, {%1,%2};" : "=l"(r) : "f"(a), "f"(b)); return r;
}
__device__ __forceinline__ void ffma2(ull& acc, ull a, ull b) {
    asm("fma.rn.f32x2 %0, %1, %2, %0;" : "+l"(acc) : "l"(a), "l"(b));
}
__device__ __forceinline__ void unpack2(ull v, float& lo, float& hi) {
    asm("mov.b64 {%0,%1}, %2;" : "=f"(lo), "=f"(hi) : "l"(v));
}

// ------------- merged prep: gru pack | fused edge MLP ---------------------
__global__ void prep_all_k(const float* __restrict__ wh, const float* __restrict__ b,
                           const float* __restrict__ w1, const float* __restrict__ b1,
                           const float* __restrict__ w2, const float* __restrict__ b2) {
    int idx = blockIdx.x * 256 + threadIdx.x;
    if (idx < 12288) {
        int k = idx & 3;
        int q = idx >> 2;           // quad index = (i*3 + g)*16 + jg
        int jg = q & 15;
        int g  = (q >> 4) % 3;
        int i  = (q >> 4) / 3;
        g_wpack[idx] = wh[i * 192 + g * 64 + jg * 4 + k];
    } else if (idx < 12480) {
        int r = idx - 12288;
        int k = r & 3;
        int g = (r >> 2) % 3;
        int jg = (r >> 2) / 3;
        g_b1pack[r] = b[192 + g * 64 + jg * 4 + k];
    } else if (idx < 12480 + 4096) {
        int r = idx - 12480;
        int c = r >> 5, j = r & 31;
        float acc = 0.0f;
        #pragma unroll
        for (int k = 0; k < 32; k++) acc += w1[c * 32 + k] * w2[k * 32 + j];
        g_We[r] = acc;
    } else if (idx < 12480 + 4128) {
        int j = idx - 12480 - 4096;
        float acc = b2[j];
        #pragma unroll
        for (int k = 0; k < 32; k++) acc += b1[k] * w2[k * 32 + j];
        g_be[j] = acc;
    }
}

// -------------- init: path state + zero m (float4) ------------------------
__global__ void init4_k(const float* __restrict__ pi) {
    int idx = blockIdx.x * 256 + threadIdx.x;   // 1,120,000 quads
    if (idx < 800000) {
        int p = idx >> 4, q = idx & 15;
        float4 v = make_float4(0.f, 0.f, 0.f, 0.f);
        if (q == 0) { v.x = pi[p]; v.y = pi[NP + p]; }
        ((float4*)g_path)[idx] = v;
    } else {
        ((float4*)g_m)[idx - 800000] = make_float4(0.f, 0.f, 0.f, 0.f);
    }
}

// ------ iter-1 Lx/Nx fast path (states rank-1: only col 0 nonzero) --------
__global__ void __launch_bounds__(192) lxnx1_kernel(const float* __restrict__ wx,
                                                    const float* __restrict__ b,
                                                    const float* __restrict__ li,
                                                    const float* __restrict__ ni) {
    int tid = threadIdx.x;
    bool is_link = (blockIdx.x < 2500);
    int base = is_link ? blockIdx.x * 8 : (blockIdx.x - 2500) * 8;
    float wj = is_link ? wx[tid] : wx[6144 + tid];
    float bj = is_link ? b[tid] : 0.0f;
    const float* init = is_link ? li : ni;
    float* dst = is_link ? g_Lx : g_Nx;
    #pragma unroll
    for (int e = 0; e < 8; e++) {
        float v = init[base + e];
        dst[(size_t)(base + e) * 192 + tid] = v * wj + bj;
    }
}

// ---------- iter-2 node Nx (post-ECC): 625 blocks ------------------------
__global__ void __launch_bounds__(192) nx2_kernel(const float* __restrict__ wx) {
    __shared__ float swx[6144];
    __shared__ float sst[8][33];
    int tid = threadIdx.x;
    for (int r = tid; r < 6144; r += 192) swx[r] = wx[6144 + r];
    int base = blockIdx.x * 8;
    for (int r = tid; r < 256; r += 192) {
        int e = r >> 5, c = r & 31;
        sst[e][c] = g_node1[(size_t)(base + e) * 32 + c];
    }
    __syncthreads();
    int j = tid;
    for (int e = 0; e < 8; e++) {
        float acc = 0.0f;
        #pragma unroll
        for (int i = 0; i < 32; i++) acc += sst[e][i] * swx[i * 192 + j];
        g_Nx[(size_t)(base + e) * 192 + j] = acc;
    }
}

// --------------------------- fused GRU scan ------------------------------
#define GRU_SMEM_BYTES 84736

#define GRU_SUB(i, v0, v1, v2, v3)                                           \
    {                                                                        \
        ulonglong2 wz = w2m[((i) * 3 + 0) * 16 + jg];                        \
        ulonglong2 wr = w2m[((i) * 3 + 1) * 16 + jg];                        \
        ulonglong2 wh = w2m[((i) * 3 + 2) * 16 + jg];                        \
        ull hp0 = pack2(v0, v0);                                             \
        ull hp1 = pack2(v1, v1);                                             \
        ull hp2 = pack2(v2, v2);                                             \
        ull hp3 = pack2(v3, v3);                                             \
        ffma2(a2[0][0], hp0, wz.x); ffma2(a2[0][1], hp0, wz.y);              \
        ffma2(a2[0][2], hp0, wr.x); ffma2(a2[0][3], hp0, wr.y);              \
        ffma2(a2[0][4], hp0, wh.x); ffma2(a2[0][5], hp0, wh.y);              \
        ffma2(a2[1][0], hp1, wz.x); ffma2(a2[1][1], hp1, wz.y);              \
        ffma2(a2[1][2], hp1, wr.x); ffma2(a2[1][3], hp1, wr.y);              \
        ffma2(a2[1][4], hp1, wh.x); ffma2(a2[1][5], hp1, wh.y);              \
        ffma2(a2[2][0], hp2, wz.x); ffma2(a2[2][1], hp2, wz.y);              \
        ffma2(a2[2][2], hp2, wr.x); ffma2(a2[2][3], hp2, wr.y);              \
        ffma2(a2[2][4], hp2, wh.x); ffma2(a2[2][5], hp2, wh.y);              \
        ffma2(a2[3][0], hp3, wz.x); ffma2(a2[3][1], hp3, wz.y);              \
        ffma2(a2[3][2], hp3, wr.x); ffma2(a2[3][3], hp3, wr.y);              \
        ffma2(a2[3][4], hp3, wh.x); ffma2(a2[3][5], hp3, wh.y);              \
    }

template <int SCATTER, int FIRST, int FINAL>
__global__ void __launch_bounds__(256, 2) gru_kernel(
    const int* __restrict__ l2p, const int* __restrict__ n2p,
    const float* __restrict__ rw1, const float* __restrict__ rb1,
    const float* __restrict__ rw2, const float* __restrict__ rb2,
    const float* __restrict__ fw,  const float* __restrict__ fb,
    float* __restrict__ out) {
    extern __shared__ float sm[];
    float4* wsm = (float4*)sm;               // 3072 quads
    float*  sb1 = sm + 12288;                // 192
    float*  shh = sm + 12480;                // 2 * 4352  ([p][68] layout)

    int tid = threadIdx.x;
    int pg = tid >> 4, jg = tid & 15;
    int pbase = blockIdx.x * 64;

    const float4* wgl = (const float4*)g_wpack;
    #pragma unroll
    for (int r = 0; r < 12; r++) wsm[r * 256 + tid] = wgl[r * 256 + tid];
    if (tid < 192) sb1[tid] = g_b1pack[tid];

    const float4* gp4 = (const float4*)g_path;
    #pragma unroll
    for (int r = 0; r < 4; r++) {
        int idx = r * 256 + tid;
        int p = idx >> 4, iq = idx & 15;
        int pglob = pbase + p; if (pglob >= NP) pglob = NP - 1;
        float4 v = gp4[(size_t)pglob * 16 + iq];
        *(float4*)(shh + p * 68 + iq * 4) = v;
    }
    __syncthreads();

    const ulonglong2* sb2 = (const ulonglong2*)sb1;
    ulonglong2 bA = sb2[jg * 3 + 0];
    ulonglong2 bB = sb2[jg * 3 + 1];
    ulonglong2 bC = sb2[jg * 3 + 2];

    int pid[4]; bool pv[4];
    #pragma unroll
    for (int pp = 0; pp < 4; pp++) {
        int pglob = pbase + pg * 4 + pp;
        pv[pp] = (pglob < NP);
        pid[pp] = pv[pp] ? pglob : NP - 1;
    }
    const int hb0 = (pg * 4 + 0) * 68;
    const int hb1 = (pg * 4 + 1) * 68;
    const int hb2 = (pg * 4 + 2) * 68;
    const int hb3 = (pg * 4 + 3) * 68;

    const float4* Lx4 = (const float4*)g_Lx;
    const float4* Nx4 = (const float4*)g_Nx;
    const ulonglong2* w2m = (const ulonglong2*)wsm;

    int hbuf = 0;
    for (int t = 0; t < 8; t++) {
        float4 gz[4], gr[4], gc[4];
        int liA[4];
        #pragma unroll
        for (int pp = 0; pp < 4; pp++) {
            int e = pid[pp] * 8 + t;
            int li = l2p[e], ni = n2p[e];
            liA[pp] = li;
            const float4* lq = Lx4 + (size_t)li * 48 + jg;
            const float4* nq = Nx4 + (size_t)ni * 48 + jg;
            float4 a0 = lq[0],  b0 = nq[0];
            float4 a1 = lq[16], b1 = nq[16];
            float4 a2q = lq[32], b2q = nq[32];
            gz[pp] = make_float4(a0.x + b0.x, a0.y + b0.y, a0.z + b0.z, a0.w + b0.w);
            gr[pp] = make_float4(a1.x + b1.x, a1.y + b1.y, a1.z + b1.z, a1.w + b1.w);
            gc[pp] = make_float4(a2q.x + b2q.x, a2q.y + b2q.y, a2q.z + b2q.z, a2q.w + b2q.w);
        }

        float* shH  = shh + hbuf * 4352;
        float* shHn = shh + (hbuf ^ 1) * 4352;

        ull a2[4][6];
        #pragma unroll
        for (int pp = 0; pp < 4; pp++) {
            a2[pp][0] = bA.x; a2[pp][1] = bA.y;
            a2[pp][2] = bB.x; a2[pp][3] = bB.y;
            a2[pp][4] = bC.x; a2[pp][5] = bC.y;
        }

        if (FIRST && t == 0) {
            float2 h20 = *(const float2*)(shH + hb0);
            float2 h21 = *(const float2*)(shH + hb1);
            float2 h22 = *(const float2*)(shH + hb2);
            float2 h23 = *(const float2*)(shH + hb3);
            GRU_SUB(0, h20.x, h21.x, h22.x, h23.x);
            GRU_SUB(1, h20.y, h21.y, h22.y, h23.y);
        } else {
            #pragma unroll 2
            for (int i4 = 0; i4 < 64; i4 += 4) {
                float4 h40 = *(const float4*)(shH + hb0 + i4);
                float4 h41 = *(const float4*)(shH + hb1 + i4);
                float4 h42 = *(const float4*)(shH + hb2 + i4);
                float4 h43 = *(const float4*)(shH + hb3 + i4);
                GRU_SUB(i4 + 0, h40.x, h41.x, h42.x, h43.x);
                GRU_SUB(i4 + 1, h40.y, h41.y, h42.y, h43.y);
                GRU_SUB(i4 + 2, h40.z, h41.z, h42.z, h43.z);
                GRU_SUB(i4 + 3, h40.w, h41.w, h42.w, h43.w);
            }
        }

        int j0 = jg * 4;
        #pragma unroll
        for (int pp = 0; pp < 4; pp++) {
            int p = pg * 4 + pp;
            float az0, az1, az2, az3, ar0, ar1, ar2, ar3, ah0, ah1, ah2, ah3;
            unpack2(a2[pp][0], az0, az1); unpack2(a2[pp][1], az2, az3);
            unpack2(a2[pp][2], ar0, ar1); unpack2(a2[pp][3], ar2, ar3);
            unpack2(a2[pp][4], ah0, ah1); unpack2(a2[pp][5], ah2, ah3);
            float z0 = sigm(gz[pp].x + az0);
            float z1 = sigm(gz[pp].y + az1);
            float z2 = sigm(gz[pp].z + az2);
            float z3 = sigm(gz[pp].w + az3);
            float r0 = sigm(gr[pp].x + ar0);
            float r1 = sigm(gr[pp].y + ar1);
            float r2 = sigm(gr[pp].z + ar2);
            float r3 = sigm(gr[pp].w + ar3);
            float c0 = tanh_fast(gc[pp].x + r0 * ah0);
            float c1 = tanh_fast(gc[pp].y + r1 * ah1);
            float c2 = tanh_fast(gc[pp].z + r2 * ah2);
            float c3 = tanh_fast(gc[pp].w + r3 * ah3);
            float4 hold = *(const float4*)(shH + p * 68 + j0);
            float n0 = z0 * hold.x + (1.0f - z0) * c0;
            float n1 = z1 * hold.y + (1.0f - z1) * c1;
            float n2 = z2 * hold.z + (1.0f - z2) * c2;
            float n3 = z3 * hold.w + (1.0f - z3) * c3;
            *(float4*)(shHn + p * 68 + j0) = make_float4(n0, n1, n2, n3);
            if (SCATTER && pv[pp]) {
                red4(g_m + (size_t)liA[pp] * 64 + j0, n0, n1, n2, n3);
            }
        }
        hbuf ^= 1;
        __syncthreads();
    }

    float* shF = shh + hbuf * 4352;

    if (!FINAL) {
        #pragma unroll
        for (int r = 0; r < 4; r++) {
            int idx = r * 256 + tid;
            int p = idx >> 4, iq = idx & 15;
            int pglob = pbase + p;
            if (pglob < NP) {
                float4 v = *(const float4*)(shF + p * 68 + iq * 4);
                ((float4*)g_path)[(size_t)pglob * 16 + iq] = v;
            }
        }
    } else {
        // ---- inline readout (overwrite weight smem; h already in shF) ----
        float* sw1  = sm;            // 2048
        float* sw2  = sm + 2048;     // 1024
        float* sfw  = sm + 3072;     // 96
        float* srb1 = sm + 3200;     // 32
        float* srb2 = sm + 3232;     // 32
        float* sr1a = sm + 3264;     // 8 * 33
        for (int r = tid; r < 2048; r += 256) sw1[r] = rw1[r];
        for (int r = tid; r < 1024; r += 256) sw2[r] = rw2[r];
        if (tid < 96) sfw[tid] = fw[tid];
        if (tid < 32) srb1[tid] = rb1[tid];
        else if (tid < 64) srb2[tid - 32] = rb2[tid - 32];
        __syncthreads();
        int w = tid >> 5, lane = tid & 31;
        float rb1l = srb1[lane], rb2l = srb2[lane], fb0 = fb[0];
        #pragma unroll
        for (int it = 0; it < 8; it++) {
            int pl = w * 8 + it;
            int pglob = pbase + pl;
            const float* hrow = shF + pl * 68;
            float acc = rb1l;
            #pragma unroll
            for (int i = 0; i < 64; i++) acc += hrow[i] * sw1[i * 32 + lane];
            float r1v = selu_f(acc);
            sr1a[w * 33 + lane] = r1v;
            __syncwarp();
            float acc2 = rb2l;
            #pragma unroll
            for (int i = 0; i < 32; i++) acc2 += sr1a[w * 33 + i] * sw2[i * 32 + lane];
            float r2v = selu_f(acc2);
            float part = r2v * sfw[lane] + hrow[lane] * sfw[32 + lane]
                       + hrow[32 + lane] * sfw[64 + lane];
            #pragma unroll
            for (int o = 16; o; o >>= 1) part += __shfl_down_sync(0xffffffffu, part, o);
            if (lane == 0 && pglob < NP) out[pglob] = part + fb0;
            __syncwarp();
        }
    }
}

// --------- root (rank-1): node1 = broot + ni * wroot_row0 -----------------
__global__ void __launch_bounds__(256) root2_kernel(const float* __restrict__ wroot,
                                                    const float* __restrict__ broot,
                                                    const float* __restrict__ ni_in) {
    int tid = threadIdx.x;
    int w = tid >> 5, lane = tid & 31;
    int n = blockIdx.x * 8 + w;
    g_node1[(size_t)n * 32 + lane] = broot[lane] + ni_in[n] * wroot[lane];
}

// ----- fused edge MLP + ECC msg + iter-2 Lx: 32 links/block (amortized) ---
#define EDGE_SMEM_BYTES 58368
__global__ void __launch_bounds__(256) edge_msg_lx_kernel(
    const int* __restrict__ l2n, const int* __restrict__ senders,
    const int* __restrict__ recv, const float* __restrict__ wx,
    const float* __restrict__ gb, const float* __restrict__ wk,
    const float* __restrict__ bk, const float* __restrict__ li_in,
    const float* __restrict__ ni_in) {
    extern __shared__ float es[];
    float* sWe  = es;            // 4096
    float* swxL = es + 4096;     // 6144
    float* sbx  = es + 10240;    // 192
    float* sbe  = es + 10432;    // 32
    float* swk  = es + 10464;    // 1024  (swk[c*32+o] = wk[c*1024+o])
    float* sbk  = es + 11488;    // 32
    float* con  = es + 11520;    // 32*64
    float* sL   = es + 13568;    // 32*32
    int tid = threadIdx.x;
    for (int i = tid; i < 4096; i += 256) sWe[i] = g_We[i];
    for (int i = tid; i < 6144; i += 256) swxL[i] = wx[i];
    for (int i = tid; i < 1024; i += 256) {
        int c = i >> 5, o = i & 31;
        swk[i] = wk[c * 1024 + o];
    }
    if (tid < 192) sbx[tid] = gb[tid];
    if (tid < 32) sbe[tid] = g_be[tid];
    else if (tid < 64) sbk[tid - 32] = bk[tid - 32];
    int w = tid >> 5, lane = tid & 31;
    int lbase = blockIdx.x * 32;
    // stage m tile: 32 links x 64 floats = 512 float4, contiguous
    for (int i = tid; i < 512; i += 256)
        ((float4*)con)[i] = ((const float4*)g_m)[(size_t)lbase * 16 + i];
    __syncthreads();
    #pragma unroll
    for (int q = 0; q < 4; q++) {
        int lloc = w * 4 + q;
        int l = lbase + lloc;
        float n0 = ni_in[l2n[l]];
        float lv = li_in[l];
        // edge MLP: exact-zero columns of con skipped (bit-exact)
        float acc = sbe[lane] + n0 * sWe[lane];
        acc += lv * sWe[1024 + lane];
        #pragma unroll
        for (int k = 0; k < 64; k++) acc += con[lloc * 64 + k] * sWe[(64 + k) * 32 + lane];
        sL[lloc * 32 + lane] = acc;
    }
    __syncwarp();
    #pragma unroll
    for (int q = 0; q < 4; q++) {
        int lloc = w * 4 + q;
        int l = lbase + lloc;
        // ECC message (rank-1 sender): msg = ns * (bk_row0 + sum_c L'_c wk[c,0,o])
        float ns = ni_in[senders[l]];
        float qq = sbk[lane];
        #pragma unroll
        for (int c = 0; c < 32; c++) qq += sL[lloc * 32 + c] * swk[c * 32 + lane];
        atomicAdd(&g_node1[(size_t)recv[l] * 32 + lane], ns * qq);
        // iter-2 link Lx from link'
        #pragma unroll
        for (int k = 0; k < 6; k++) {
            int jj = k * 32 + lane;
            float a = sbx[jj];
            #pragma unroll
            for (int c = 0; c < 32; c++) a += sL[lloc * 32 + c] * swxL[c * 192 + jj];
            g_Lx[(size_t)l * 192 + jj] = a;
        }
    }
}

// ---------------------------- launcher ------------------------------------
extern "C" void kernel_launch(void* const* d_in, const int* in_sizes, int n_in,
                              void* d_out, int out_size) {
    const float* link_init = (const float*)d_in[0];
    const float* node_init = (const float*)d_in[1];
    const float* path_init = (const float*)d_in[2];
    const float* gru_wx    = (const float*)d_in[3];
    const float* gru_wh    = (const float*)d_in[4];
    const float* gru_b     = (const float*)d_in[5];
    const float* e_w1      = (const float*)d_in[6];
    const float* e_b1      = (const float*)d_in[7];
    const float* e_w2      = (const float*)d_in[8];
    const float* e_b2      = (const float*)d_in[9];
    const float* ecc_wk    = (const float*)d_in[10];
    const float* ecc_bk    = (const float*)d_in[11];
    const float* ecc_wroot = (const float*)d_in[12];
    const float* ecc_broot = (const float*)d_in[13];
    const float* r_w1      = (const float*)d_in[14];
    const float* r_b1      = (const float*)d_in[15];
    const float* r_w2      = (const float*)d_in[16];
    const float* r_b2      = (const float*)d_in[17];
    const float* f_w       = (const float*)d_in[18];
    const float* f_b       = (const float*)d_in[19];
    const int* l2p   = (const int*)d_in[22];
    const int* n2p   = (const int*)d_in[23];
    const int* l2n   = (const int*)d_in[24];
    const int* senders   = (const int*)d_in[25];
    const int* receivers = (const int*)d_in[26];
    float* out = (float*)d_out;

    cudaFuncSetAttribute((const void*)gru_kernel<1, 1, 0>,
                         cudaFuncAttributeMaxDynamicSharedMemorySize, GRU_SMEM_BYTES);
    cudaFuncSetAttribute((const void*)gru_kernel<0, 0, 1>,
                         cudaFuncAttributeMaxDynamicSharedMemorySize, GRU_SMEM_BYTES);
    cudaFuncSetAttribute((const void*)edge_msg_lx_kernel,
                         cudaFuncAttributeMaxDynamicSharedMemorySize, EDGE_SMEM_BYTES);

    prep_all_k<<<65, 256>>>(gru_wh, gru_b, e_w1, e_b1, e_w2, e_b2);            // 0
    init4_k<<<4375, 256>>>(path_init);                                         // 1
    lxnx1_kernel<<<3125, 192>>>(gru_wx, gru_b, link_init, node_init);          // 2
    gru_kernel<1, 1, 0><<<782, 256, GRU_SMEM_BYTES>>>(
        l2p, n2p, r_w1, r_b1, r_w2, r_b2, f_w, f_b, out);                      // 3
    root2_kernel<<<625, 256>>>(ecc_wroot, ecc_broot, node_init);               // 4
    edge_msg_lx_kernel<<<625, 256, EDGE_SMEM_BYTES>>>(
        l2n, senders, receivers, gru_wx, gru_b, ecc_wk, ecc_bk,
        link_init, node_init);                                                 // 5
    nx2_kernel<<<625, 192>>>(gru_wx);                                          // 6
    gru_kernel<0, 0, 1><<<782, 256, GRU_SMEM_BYTES>>>(
        l2p, n2p, r_w1, r_b1, r_w2, r_b2, f_w, f_b, out);                      // 7
}

// round 17
// speedup vs baseline: 1.0893x; 1.0064x over previous
#include <cuda_runtime.h>
#include <math.h>

#define NN 5000
#define NL 20000
#define NP 50000

typedef unsigned long long ull;

// ------------------------- device-global scratch -------------------------
__device__ __align__(16) float g_node1[NN * 32];      // ECC msg accumulator
__device__ __align__(16) float g_path[NP * 64];
__device__ __align__(16) float g_m[NL * 64];
__device__ __align__(16) float g_Lx[NL * 192];
__device__ __align__(16) float g_Nx[NN * 192];
__device__ __align__(16) float g_wpack[12288];
__device__ __align__(16) float g_b1pack[192];
__device__ __align__(16) float g_We[4096];
__device__ __align__(16) float g_be[32];

// ------------------------------ helpers ----------------------------------
__device__ __forceinline__ float sigm(float x) {
    return __fdividef(1.0f, 1.0f + __expf(-x));
}
__device__ __forceinline__ float tanh_fast(float x) {
    float ax = fabsf(x);
    float e  = __expf(-2.0f * ax);
    float t  = __fdividef(1.0f - e, 1.0f + e);
    return copysignf(t, x);
}
__device__ __forceinline__ float selu_f(float x) {
    return x > 0.0f ? 1.0507009873554805f * x
                    : 1.7580993408473766f * (__expf(x) - 1.0f);
}
__device__ __forceinline__ void red4(float* a, float x, float y, float z, float w) {
    asm volatile("red.global.add.v4.f32 [%0], {%1,%2,%3,%4};"
                 :: "l"(a), "f"(x), "f"(y), "f"(z), "f"(w) : "memory");
}
__device__ __forceinline__ ull pack2(float a, float b) {
    ull r; asm("mov.b64 %0, {%1,%2};" : "=l"(r) : "f"(a), "f"(b)); return r;
}
__device__ __forceinline__ void ffma2(ull& acc, ull a, ull b) {
    asm("fma.rn.f32x2 %0, %1, %2, %0;" : "+l"(acc) : "l"(a), "l"(b));
}
__device__ __forceinline__ void unpack2(ull v, float& lo, float& hi) {
    asm("mov.b64 {%0,%1}, %2;" : "=f"(lo), "=f"(hi) : "l"(v));
}

// ===== merged setup: lxnx1 | init(path,m,node1-zero) | prep(wpack,We) =====
// blocks [0,3125): iter-1 Lx/Nx rank-1 fast path (192 active threads)
// blocks [3125,7657): init quads (path 800000 | m 320000 | node1 40000)
// blocks [7657,7722): weight prep (16608 elements)
__global__ void __launch_bounds__(256) setup_k(
    const float* __restrict__ wx,  const float* __restrict__ gb,
    const float* __restrict__ li,  const float* __restrict__ ni,
    const float* __restrict__ pi,  const float* __restrict__ wh,
    const float* __restrict__ w1,  const float* __restrict__ b1,
    const float* __restrict__ w2,  const float* __restrict__ b2) {
    int blk = blockIdx.x;
    int tid = threadIdx.x;
    if (blk < 3125) {
        if (tid < 192) {
            bool is_link = (blk < 2500);
            int base = is_link ? blk * 8 : (blk - 2500) * 8;
            float wj = is_link ? wx[tid] : wx[6144 + tid];
            float bj = is_link ? gb[tid] : 0.0f;
            const float* init = is_link ? li : ni;
            float* dst = is_link ? g_Lx : g_Nx;
            #pragma unroll
            for (int e = 0; e < 8; e++) {
                float v = init[base + e];
                dst[(size_t)(base + e) * 192 + tid] = v * wj + bj;
            }
        }
    } else if (blk < 7657) {
        int idx = (blk - 3125) * 256 + tid;
        if (idx < 800000) {
            int p = idx >> 4, q = idx & 15;
            float4 v = make_float4(0.f, 0.f, 0.f, 0.f);
            if (q == 0) { v.x = pi[p]; v.y = pi[NP + p]; }
            ((float4*)g_path)[idx] = v;
        } else if (idx < 1120000) {
            ((float4*)g_m)[idx - 800000] = make_float4(0.f, 0.f, 0.f, 0.f);
        } else if (idx < 1160000) {
            ((float4*)g_node1)[idx - 1120000] = make_float4(0.f, 0.f, 0.f, 0.f);
        }
    } else {
        int idx = (blk - 7657) * 256 + tid;
        if (idx < 12288) {
            int k = idx & 3;
            int q = idx >> 2;           // quad index = (i*3 + g)*16 + jg
            int jg = q & 15;
            int g  = (q >> 4) % 3;
            int i  = (q >> 4) / 3;
            g_wpack[idx] = wh[i * 192 + g * 64 + jg * 4 + k];
        } else if (idx < 12480) {
            int r = idx - 12288;
            int k = r & 3;
            int g = (r >> 2) % 3;
            int jg = (r >> 2) / 3;
            g_b1pack[r] = gb[192 + g * 64 + jg * 4 + k];
        } else if (idx < 12480 + 4096) {
            int r = idx - 12480;
            int c = r >> 5, j = r & 31;
            float acc = 0.0f;
            #pragma unroll
            for (int k = 0; k < 32; k++) acc += w1[c * 32 + k] * w2[k * 32 + j];
            g_We[r] = acc;
        } else if (idx < 12480 + 4128) {
            int j = idx - 12480 - 4096;
            float acc = b2[j];
            #pragma unroll
            for (int k = 0; k < 32; k++) acc += b1[k] * w2[k * 32 + j];
            g_be[j] = acc;
        }
    }
}

// ---------- iter-2 node Nx: node1 = msg-acc + broot + ni*wroot_row0 -------
__global__ void __launch_bounds__(192) nx2_kernel(const float* __restrict__ wx,
                                                  const float* __restrict__ wroot,
                                                  const float* __restrict__ broot,
                                                  const float* __restrict__ ni_in) {
    __shared__ float swx[6144];
    __shared__ float sst[8][33];
    int tid = threadIdx.x;
    for (int r = tid; r < 6144; r += 192) swx[r] = wx[6144 + r];
    int base = blockIdx.x * 8;
    for (int r = tid; r < 256; r += 192) {
        int e = r >> 5, c = r & 31;
        sst[e][c] = g_node1[(size_t)(base + e) * 32 + c] + broot[c]
                  + ni_in[base + e] * wroot[c];
    }
    __syncthreads();
    int j = tid;
    for (int e = 0; e < 8; e++) {
        float acc = 0.0f;
        #pragma unroll
        for (int i = 0; i < 32; i++) acc += sst[e][i] * swx[i * 192 + j];
        g_Nx[(size_t)(base + e) * 192 + j] = acc;
    }
}

// --------------------------- fused GRU scan ------------------------------
#define GRU_SMEM_BYTES 84736

#define GRU_SUB(i, v0, v1, v2, v3)                                           \
    {                                                                        \
        ulonglong2 wz = w2m[((i) * 3 + 0) * 16 + jg];                        \
        ulonglong2 wr = w2m[((i) * 3 + 1) * 16 + jg];                        \
        ulonglong2 wh = w2m[((i) * 3 + 2) * 16 + jg];                        \
        ull hp0 = pack2(v0, v0);                                             \
        ull hp1 = pack2(v1, v1);                                             \
        ull hp2 = pack2(v2, v2);                                             \
        ull hp3 = pack2(v3, v3);                                             \
        ffma2(a2[0][0], hp0, wz.x); ffma2(a2[0][1], hp0, wz.y);              \
        ffma2(a2[0][2], hp0, wr.x); ffma2(a2[0][3], hp0, wr.y);              \
        ffma2(a2[0][4], hp0, wh.x); ffma2(a2[0][5], hp0, wh.y);              \
        ffma2(a2[1][0], hp1, wz.x); ffma2(a2[1][1], hp1, wz.y);              \
        ffma2(a2[1][2], hp1, wr.x); ffma2(a2[1][3], hp1, wr.y);              \
        ffma2(a2[1][4], hp1, wh.x); ffma2(a2[1][5], hp1, wh.y);              \
        ffma2(a2[2][0], hp2, wz.x); ffma2(a2[2][1], hp2, wz.y);              \
        ffma2(a2[2][2], hp2, wr.x); ffma2(a2[2][3], hp2, wr.y);              \
        ffma2(a2[2][4], hp2, wh.x); ffma2(a2[2][5], hp2, wh.y);              \
        ffma2(a2[3][0], hp3, wz.x); ffma2(a2[3][1], hp3, wz.y);              \
        ffma2(a2[3][2], hp3, wr.x); ffma2(a2[3][3], hp3, wr.y);              \
        ffma2(a2[3][4], hp3, wh.x); ffma2(a2[3][5], hp3, wh.y);              \
    }

template <int SCATTER, int FIRST, int FINAL>
__global__ void __launch_bounds__(256, 2) gru_kernel(
    const int* __restrict__ l2p, const int* __restrict__ n2p,
    const float* __restrict__ rw1, const float* __restrict__ rb1,
    const float* __restrict__ rw2, const float* __restrict__ rb2,
    const float* __restrict__ fw,  const float* __restrict__ fb,
    float* __restrict__ out) {
    extern __shared__ float sm[];
    float4* wsm = (float4*)sm;               // 3072 quads
    float*  sb1 = sm + 12288;                // 192
    float*  shh = sm + 12480;                // 2 * 4352  ([p][68] layout)

    int tid = threadIdx.x;
    int pg = tid >> 4, jg = tid & 15;
    int pbase = blockIdx.x * 64;

    const float4* wgl = (const float4*)g_wpack;
    #pragma unroll
    for (int r = 0; r < 12; r++) wsm[r * 256 + tid] = wgl[r * 256 + tid];
    if (tid < 192) sb1[tid] = g_b1pack[tid];

    const float4* gp4 = (const float4*)g_path;
    #pragma unroll
    for (int r = 0; r < 4; r++) {
        int idx = r * 256 + tid;
        int p = idx >> 4, iq = idx & 15;
        int pglob = pbase + p; if (pglob >= NP) pglob = NP - 1;
        float4 v = gp4[(size_t)pglob * 16 + iq];
        *(float4*)(shh + p * 68 + iq * 4) = v;
    }
    __syncthreads();

    const ulonglong2* sb2 = (const ulonglong2*)sb1;
    ulonglong2 bA = sb2[jg * 3 + 0];
    ulonglong2 bB = sb2[jg * 3 + 1];
    ulonglong2 bC = sb2[jg * 3 + 2];

    int pid[4]; bool pv[4];
    #pragma unroll
    for (int pp = 0; pp < 4; pp++) {
        int pglob = pbase + pg * 4 + pp;
        pv[pp] = (pglob < NP);
        pid[pp] = pv[pp] ? pglob : NP - 1;
    }
    const int hb0 = (pg * 4 + 0) * 68;
    const int hb1 = (pg * 4 + 1) * 68;
    const int hb2 = (pg * 4 + 2) * 68;
    const int hb3 = (pg * 4 + 3) * 68;

    const float4* Lx4 = (const float4*)g_Lx;
    const float4* Nx4 = (const float4*)g_Nx;
    const ulonglong2* w2m = (const ulonglong2*)wsm;

    int hbuf = 0;
    for (int t = 0; t < 8; t++) {
        float4 gz[4], gr[4], gc[4];
        int liA[4];
        #pragma unroll
        for (int pp = 0; pp < 4; pp++) {
            int e = pid[pp] * 8 + t;
            int li = l2p[e], ni = n2p[e];
            liA[pp] = li;
            const float4* lq = Lx4 + (size_t)li * 48 + jg;
            const float4* nq = Nx4 + (size_t)ni * 48 + jg;
            float4 a0 = lq[0],  b0 = nq[0];
            float4 a1 = lq[16], b1 = nq[16];
            float4 a2q = lq[32], b2q = nq[32];
            gz[pp] = make_float4(a0.x + b0.x, a0.y + b0.y, a0.z + b0.z, a0.w + b0.w);
            gr[pp] = make_float4(a1.x + b1.x, a1.y + b1.y, a1.z + b1.z, a1.w + b1.w);
            gc[pp] = make_float4(a2q.x + b2q.x, a2q.y + b2q.y, a2q.z + b2q.z, a2q.w + b2q.w);
        }

        float* shH  = shh + hbuf * 4352;
        float* shHn = shh + (hbuf ^ 1) * 4352;

        ull a2[4][6];
        #pragma unroll
        for (int pp = 0; pp < 4; pp++) {
            a2[pp][0] = bA.x; a2[pp][1] = bA.y;
            a2[pp][2] = bB.x; a2[pp][3] = bB.y;
            a2[pp][4] = bC.x; a2[pp][5] = bC.y;
        }

        if (FIRST && t == 0) {
            float2 h20 = *(const float2*)(shH + hb0);
            float2 h21 = *(const float2*)(shH + hb1);
            float2 h22 = *(const float2*)(shH + hb2);
            float2 h23 = *(const float2*)(shH + hb3);
            GRU_SUB(0, h20.x, h21.x, h22.x, h23.x);
            GRU_SUB(1, h20.y, h21.y, h22.y, h23.y);
        } else {
            #pragma unroll 2
            for (int i4 = 0; i4 < 64; i4 += 4) {
                float4 h40 = *(const float4*)(shH + hb0 + i4);
                float4 h41 = *(const float4*)(shH + hb1 + i4);
                float4 h42 = *(const float4*)(shH + hb2 + i4);
                float4 h43 = *(const float4*)(shH + hb3 + i4);
                GRU_SUB(i4 + 0, h40.x, h41.x, h42.x, h43.x);
                GRU_SUB(i4 + 1, h40.y, h41.y, h42.y, h43.y);
                GRU_SUB(i4 + 2, h40.z, h41.z, h42.z, h43.z);
                GRU_SUB(i4 + 3, h40.w, h41.w, h42.w, h43.w);
            }
        }

        int j0 = jg * 4;
        #pragma unroll
        for (int pp = 0; pp < 4; pp++) {
            int p = pg * 4 + pp;
            float az0, az1, az2, az3, ar0, ar1, ar2, ar3, ah0, ah1, ah2, ah3;
            unpack2(a2[pp][0], az0, az1); unpack2(a2[pp][1], az2, az3);
            unpack2(a2[pp][2], ar0, ar1); unpack2(a2[pp][3], ar2, ar3);
            unpack2(a2[pp][4], ah0, ah1); unpack2(a2[pp][5], ah2, ah3);
            float z0 = sigm(gz[pp].x + az0);
            float z1 = sigm(gz[pp].y + az1);
            float z2 = sigm(gz[pp].z + az2);
            float z3 = sigm(gz[pp].w + az3);
            float r0 = sigm(gr[pp].x + ar0);
            float r1 = sigm(gr[pp].y + ar1);
            float r2 = sigm(gr[pp].z + ar2);
            float r3 = sigm(gr[pp].w + ar3);
            float c0 = tanh_fast(gc[pp].x + r0 * ah0);
            float c1 = tanh_fast(gc[pp].y + r1 * ah1);
            float c2 = tanh_fast(gc[pp].z + r2 * ah2);
            float c3 = tanh_fast(gc[pp].w + r3 * ah3);
            float4 hold = *(const float4*)(shH + p * 68 + j0);
            float n0 = z0 * hold.x + (1.0f - z0) * c0;
            float n1 = z1 * hold.y + (1.0f - z1) * c1;
            float n2 = z2 * hold.z + (1.0f - z2) * c2;
            float n3 = z3 * hold.w + (1.0f - z3) * c3;
            *(float4*)(shHn + p * 68 + j0) = make_float4(n0, n1, n2, n3);
            if (SCATTER && pv[pp]) {
                red4(g_m + (size_t)liA[pp] * 64 + j0, n0, n1, n2, n3);
            }
        }
        hbuf ^= 1;
        __syncthreads();
    }

    float* shF = shh + hbuf * 4352;

    if (!FINAL) {
        #pragma unroll
        for (int r = 0; r < 4; r++) {
            int idx = r * 256 + tid;
            int p = idx >> 4, iq = idx & 15;
            int pglob = pbase + p;
            if (pglob < NP) {
                float4 v = *(const float4*)(shF + p * 68 + iq * 4);
                ((float4*)g_path)[(size_t)pglob * 16 + iq] = v;
            }
        }
    } else {
        // ---- inline readout (overwrite weight smem; h already in shF) ----
        float* sw1  = sm;            // 2048
        float* sw2  = sm + 2048;     // 1024
        float* sfw  = sm + 3072;     // 96
        float* srb1 = sm + 3200;     // 32
        float* srb2 = sm + 3232;     // 32
        float* sr1a = sm + 3264;     // 8 * 33
        for (int r = tid; r < 2048; r += 256) sw1[r] = rw1[r];
        for (int r = tid; r < 1024; r += 256) sw2[r] = rw2[r];
        if (tid < 96) sfw[tid] = fw[tid];
        if (tid < 32) srb1[tid] = rb1[tid];
        else if (tid < 64) srb2[tid - 32] = rb2[tid - 32];
        __syncthreads();
        int w = tid >> 5, lane = tid & 31;
        float rb1l = srb1[lane], rb2l = srb2[lane], fb0 = fb[0];
        #pragma unroll
        for (int it = 0; it < 8; it++) {
            int pl = w * 8 + it;
            int pglob = pbase + pl;
            const float* hrow = shF + pl * 68;
            float acc = rb1l;
            #pragma unroll
            for (int i = 0; i < 64; i++) acc += hrow[i] * sw1[i * 32 + lane];
            float r1v = selu_f(acc);
            sr1a[w * 33 + lane] = r1v;
            __syncwarp();
            float acc2 = rb2l;
            #pragma unroll
            for (int i = 0; i < 32; i++) acc2 += sr1a[w * 33 + i] * sw2[i * 32 + lane];
            float r2v = selu_f(acc2);
            float part = r2v * sfw[lane] + hrow[lane] * sfw[32 + lane]
                       + hrow[32 + lane] * sfw[64 + lane];
            #pragma unroll
            for (int o = 16; o; o >>= 1) part += __shfl_down_sync(0xffffffffu, part, o);
            if (lane == 0 && pglob < NP) out[pglob] = part + fb0;
            __syncwarp();
        }
    }
}

// ----- fused edge MLP + ECC msg + iter-2 Lx: 32 links/block (amortized) ---
#define EDGE_SMEM_BYTES 58368
__global__ void __launch_bounds__(256) edge_msg_lx_kernel(
    const int* __restrict__ l2n, const int* __restrict__ senders,
    const int* __restrict__ recv, const float* __restrict__ wx,
    const float* __restrict__ gb, const float* __restrict__ wk,
    const float* __restrict__ bk, const float* __restrict__ li_in,
    const float* __restrict__ ni_in) {
    extern __shared__ float es[];
    float* sWe  = es;            // 4096
    float* swxL = es + 4096;     // 6144
    float* sbx  = es + 10240;    // 192
    float* sbe  = es + 10432;    // 32
    float* swk  = es + 10464;    // 1024  (swk[c*32+o] = wk[c*1024+o])
    float* sbk  = es + 11488;    // 32
    float* con  = es + 11520;    // 32*64
    float* sL   = es + 13568;    // 32*32
    int tid = threadIdx.x;
    for (int i = tid; i < 4096; i += 256) sWe[i] = g_We[i];
    for (int i = tid; i < 6144; i += 256) swxL[i] = wx[i];
    for (int i = tid; i < 1024; i += 256) {
        int c = i >> 5, o = i & 31;
        swk[i] = wk[c * 1024 + o];
    }
    if (tid < 192) sbx[tid] = gb[tid];
    if (tid < 32) sbe[tid] = g_be[tid];
    else if (tid < 64) sbk[tid - 32] = bk[tid - 32];
    int w = tid >> 5, lane = tid & 31;
    int lbase = blockIdx.x * 32;
    for (int i = tid; i < 512; i += 256)
        ((float4*)con)[i] = ((const float4*)g_m)[(size_t)lbase * 16 + i];
    __syncthreads();
    #pragma unroll
    for (int q = 0; q < 4; q++) {
        int lloc = w * 4 + q;
        int l = lbase + lloc;
        float n0 = ni_in[l2n[l]];
        float lv = li_in[l];
        float acc = sbe[lane] + n0 * sWe[lane];
        acc += lv * sWe[1024 + lane];
        #pragma unroll
        for (int k = 0; k < 64; k++) acc += con[lloc * 64 + k] * sWe[(64 + k) * 32 + lane];
        sL[lloc * 32 + lane] = acc;
    }
    __syncwarp();
    #pragma unroll
    for (int q = 0; q < 4; q++) {
        int lloc = w * 4 + q;
        int l = lbase + lloc;
        float ns = ni_in[senders[l]];
        float qq = sbk[lane];
        #pragma unroll
        for (int c = 0; c < 32; c++) qq += sL[lloc * 32 + c] * swk[c * 32 + lane];
        atomicAdd(&g_node1[(size_t)recv[l] * 32 + lane], ns * qq);
        #pragma unroll
        for (int k = 0; k < 6; k++) {
            int jj = k * 32 + lane;
            float a = sbx[jj];
            #pragma unroll
            for (int c = 0; c < 32; c++) a += sL[lloc * 32 + c] * swxL[c * 192 + jj];
            g_Lx[(size_t)l * 192 + jj] = a;
        }
    }
}

// ---------------------------- launcher ------------------------------------
extern "C" void kernel_launch(void* const* d_in, const int* in_sizes, int n_in,
                              void* d_out, int out_size) {
    const float* link_init = (const float*)d_in[0];
    const float* node_init = (const float*)d_in[1];
    const float* path_init = (const float*)d_in[2];
    const float* gru_wx    = (const float*)d_in[3];
    const float* gru_wh    = (const float*)d_in[4];
    const float* gru_b     = (const float*)d_in[5];
    const float* e_w1      = (const float*)d_in[6];
    const float* e_b1      = (const float*)d_in[7];
    const float* e_w2      = (const float*)d_in[8];
    const float* e_b2      = (const float*)d_in[9];
    const float* ecc_wk    = (const float*)d_in[10];
    const float* ecc_bk    = (const float*)d_in[11];
    const float* ecc_wroot = (const float*)d_in[12];
    const float* ecc_broot = (const float*)d_in[13];
    const float* r_w1      = (const float*)d_in[14];
    const float* r_b1      = (const float*)d_in[15];
    const float* r_w2      = (const float*)d_in[16];
    const float* r_b2      = (const float*)d_in[17];
    const float* f_w       = (const float*)d_in[18];
    const float* f_b       = (const float*)d_in[19];
    const int* l2p   = (const int*)d_in[22];
    const int* n2p   = (const int*)d_in[23];
    const int* l2n   = (const int*)d_in[24];
    const int* senders   = (const int*)d_in[25];
    const int* receivers = (const int*)d_in[26];
    float* out = (float*)d_out;

    cudaFuncSetAttribute((const void*)gru_kernel<1, 1, 0>,
                         cudaFuncAttributeMaxDynamicSharedMemorySize, GRU_SMEM_BYTES);
    cudaFuncSetAttribute((const void*)gru_kernel<0, 0, 1>,
                         cudaFuncAttributeMaxDynamicSharedMemorySize, GRU_SMEM_BYTES);
    cudaFuncSetAttribute((const void*)edge_msg_lx_kernel,
                         cudaFuncAttributeMaxDynamicSharedMemorySize, EDGE_SMEM_BYTES);

    setup_k<<<7722, 256>>>(gru_wx, gru_b, link_init, node_init, path_init,
                           gru_wh, e_w1, e_b1, e_w2, e_b2);                    // 0
    gru_kernel<1, 1, 0><<<782, 256, GRU_SMEM_BYTES>>>(
        l2p, n2p, r_w1, r_b1, r_w2, r_b2, f_w, f_b, out);                      // 1
    edge_msg_lx_kernel<<<625, 256, EDGE_SMEM_BYTES>>>(
        l2n, senders, receivers, gru_wx, gru_b, ecc_wk, ecc_bk,
        link_init, node_init);                                                 // 2
    nx2_kernel<<<625, 192>>>(gru_wx, ecc_wroot, ecc_broot, node_init);         // 3
    gru_kernel<0, 0, 1><<<782, 256, GRU_SMEM_BYTES>>>(
        l2p, n2p, r_w1, r_b1, r_w2, r_b2, f_w, f_b, out);                      // 4
}